// round 1
// baseline (speedup 1.0000x reference)
#include <cuda_runtime.h>

#define NB 4096
#define ND 32
#define NK 64
#define FD 16
#define FK 16
#define NHID 128
#define NH 4
#define ALPHA 0.2f
#define NEGV (-9e15f)

#define SD   (ND*FD)          // 512
#define SKK  (NK*FK)          // 1024
#define SADJ (ND*NK)          // 2048
#define OBSW (SD+SKK+SADJ)    // 3584

// ---- smem layout (float offsets) ----
#define OFF_ADJ   0                         // 2048
#define OFF_HD    2048                      // 32*128 = 4096
#define OFF_HK    (2048+4096)               // 64*128 = 8192
#define SBASE     (2048+4096+8192)          // 14336
// phase 1 (attention / projections)
#define OFF_DRONE (SBASE)                   // 512
#define OFF_DOCK  (SBASE+512)               // 1024
#define OFF_WDOCK (SBASE+1536)              // 8192
#define OFF_VSRC  (SBASE+9728)              // 64
#define OFF_VDST  (SBASE+9792)              // 64
#define OFF_SRC   (SBASE+9856)              // 128
#define OFF_DST   (SBASE+9984)              // 256
#define OFF_C     (SBASE+10240)             // 2048 (c, later wbar)
#define OFF_ATTN  (SBASE+12288)             // 512
// phase 2 (q/k/scores) -- aliases phase-1 scratch
#define OFF_W     (SBASE)                   // 16384
#define OFF_Q     (SBASE+16384)             // 4096
#define KLD       132
#define OFF_K     (SBASE+20480)             // 64*132 = 8448
#define SMEM_FLOATS (SBASE+20480+64*KLD)    // 43264 floats = 173056 B

__device__ float g_hd[(size_t)NB*ND*NHID];  // 64 MB scratch for h_drone

__device__ __forceinline__ float eluf(float x) { return x > 0.f ? x : expm1f(x); }

__global__ void __launch_bounds__(256, 1) gat_main(
    const float* __restrict__ obs,
    const float* __restrict__ Wdr, const float* __restrict__ Wdk,
    const float* __restrict__ asrc, const float* __restrict__ adst,
    const float* __restrict__ Wad, const float* __restrict__ bad,
    const float* __restrict__ Wak, const float* __restrict__ bak,
    float* __restrict__ out_logits)
{
    extern __shared__ float sm[];
    const int b = blockIdx.x;
    const int t = threadIdx.x;
    const float* row = obs + (size_t)b * OBSW;

    // ---- load obs row + W_dock ----
    for (int i = t; i < SD;   i += 256) sm[OFF_DRONE + i] = row[i];
    for (int i = t; i < SKK;  i += 256) sm[OFF_DOCK  + i] = row[SD + i];
    for (int i = t; i < SADJ; i += 256) sm[OFF_ADJ   + i] = row[SD + SKK + i];
    for (int i = t; i < NH*FK*NHID; i += 256) sm[OFF_WDOCK + i] = Wdk[i];
    __syncthreads();

    // ---- v_src[h,f] = W_drone[h,f,:]·a_src[h], v_dst similarly ----
    if (t < 64) {
        int h = t >> 4, f = t & 15;
        const float* wp = Wdr + (h*FD + f) * NHID;
        const float* ap = asrc + h * NHID;
        float a = 0.f;
        #pragma unroll 8
        for (int k = 0; k < NHID; k++) a += wp[k] * ap[k];
        sm[OFF_VSRC + t] = a;
    } else if (t < 128) {
        int u = t - 64, h = u >> 4, f = u & 15;
        const float* wp = &sm[OFF_WDOCK + (h*FK + f) * NHID];
        const float* ap = adst + h * NHID;
        float a = 0.f;
        #pragma unroll 8
        for (int k = 0; k < NHID; k++) a += wp[k] * ap[k];
        sm[OFF_VDST + u] = a;
    }
    __syncthreads();

    // ---- src[h,n], dst[h,m] ----
    if (t < 128) {
        int h = t >> 5, n = t & 31;
        float a = 0.f;
        #pragma unroll
        for (int f = 0; f < FD; f++) a += sm[OFF_DRONE + n*FD + f] * sm[OFF_VSRC + h*FD + f];
        sm[OFF_SRC + t] = a;
    }
    {
        int h = t >> 6, m = t & 63;
        float a = 0.f;
        #pragma unroll
        for (int f = 0; f < FK; f++) a += sm[OFF_DOCK + m*FK + f] * sm[OFF_VDST + h*FK + f];
        sm[OFF_DST + t] = a;
    }
    __syncthreads();

    // ---- attention rows: softmax over m, then c[h,n,:] = attn · dock ----
    {
        const int w = t >> 5, lane = t & 31;
        for (int r = w * 16; r < w * 16 + 16; r++) {
            int h = r >> 5, n = r & 31;
            float s0 = sm[OFF_SRC + h*32 + n];
            float e1, e2;
            {
                float e = s0 + sm[OFF_DST + h*64 + lane];
                e = e > 0.f ? e : ALPHA * e;
                if (!(sm[OFF_ADJ + n*64 + lane] > 0.f)) e = NEGV;
                e1 = e;
                e = s0 + sm[OFF_DST + h*64 + lane + 32];
                e = e > 0.f ? e : ALPHA * e;
                if (!(sm[OFF_ADJ + n*64 + lane + 32] > 0.f)) e = NEGV;
                e2 = e;
            }
            float mx = fmaxf(e1, e2);
            #pragma unroll
            for (int o = 16; o > 0; o >>= 1) mx = fmaxf(mx, __shfl_xor_sync(0xffffffffu, mx, o));
            float p1 = expf(e1 - mx), p2 = expf(e2 - mx);
            float s = p1 + p2;
            #pragma unroll
            for (int o = 16; o > 0; o >>= 1) s += __shfl_xor_sync(0xffffffffu, s, o);
            float inv = 1.0f / s;
            sm[OFF_ATTN + w*64 + lane]      = p1 * inv;
            sm[OFF_ATTN + w*64 + lane + 32] = p2 * inv;
            __syncwarp();
            if (lane < 16) {
                float a = 0.f;
                #pragma unroll 8
                for (int m = 0; m < 64; m++)
                    a += sm[OFF_ATTN + w*64 + m] * sm[OFF_DOCK + m*FK + lane];
                sm[OFF_C + r*16 + lane] = a;
            }
            __syncwarp();
        }
    }
    __syncthreads();

    // ---- h_drone[n,k] = elu( (1/4) * sum_{h,f} c[h,n,f] * Wdock[h,f,k] ) ----
    {
        const int k4 = (t & 31) * 4, g = t >> 5;       // g: 0..7, n = g*4+i
        float4 acc[4];
        #pragma unroll
        for (int i = 0; i < 4; i++) acc[i] = make_float4(0.f, 0.f, 0.f, 0.f);
        for (int h = 0; h < NH; h++)
            #pragma unroll
            for (int f = 0; f < FK; f++) {
                float4 wv = *(const float4*)&sm[OFF_WDOCK + (h*FK + f)*NHID + k4];
                #pragma unroll
                for (int i = 0; i < 4; i++) {
                    float c = sm[OFF_C + ((h*32) + g*4 + i)*16 + f];
                    acc[i].x += c * wv.x; acc[i].y += c * wv.y;
                    acc[i].z += c * wv.z; acc[i].w += c * wv.w;
                }
            }
        #pragma unroll
        for (int i = 0; i < 4; i++) {
            int n = g*4 + i;
            float4 v;
            v.x = eluf(acc[i].x * 0.25f); v.y = eluf(acc[i].y * 0.25f);
            v.z = eluf(acc[i].z * 0.25f); v.w = eluf(acc[i].w * 0.25f);
            *(float4*)&sm[OFF_HD + n*NHID + k4] = v;
            *(float4*)&g_hd[((size_t)b*ND + n)*NHID + k4] = v;
        }
    }
    __syncthreads();

    // ---- wbar[f,k] = mean_h Wdock[h,f,k]  (reuse c region) ----
    for (int i = t; i < FK*NHID; i += 256) {
        int f = i >> 7, k = i & 127;
        float a = sm[OFF_WDOCK + (f)*128 + k] + sm[OFF_WDOCK + (16+f)*128 + k]
                + sm[OFF_WDOCK + (32+f)*128 + k] + sm[OFF_WDOCK + (48+f)*128 + k];
        sm[OFF_C + i] = a * 0.25f;
    }
    __syncthreads();

    // ---- h_dock[m,k] = elu( dock[m,:] · wbar[:,k] ) ----
    {
        const int k4 = (t & 31) * 4, g = t >> 5;       // m = g*8+i
        float4 acc[8];
        #pragma unroll
        for (int i = 0; i < 8; i++) acc[i] = make_float4(0.f, 0.f, 0.f, 0.f);
        #pragma unroll
        for (int f = 0; f < FK; f++) {
            float4 wv = *(const float4*)&sm[OFF_C + f*128 + k4];
            #pragma unroll
            for (int i = 0; i < 8; i++) {
                float d = sm[OFF_DOCK + (g*8 + i)*FK + f];
                acc[i].x += d * wv.x; acc[i].y += d * wv.y;
                acc[i].z += d * wv.z; acc[i].w += d * wv.w;
            }
        }
        #pragma unroll
        for (int i = 0; i < 8; i++) {
            int m = g*8 + i;
            float4 v;
            v.x = eluf(acc[i].x); v.y = eluf(acc[i].y);
            v.z = eluf(acc[i].z); v.w = eluf(acc[i].w);
            *(float4*)&sm[OFF_HK + m*NHID + k4] = v;
        }
    }
    __syncthreads();

    // ================= phase 2: q, k, scores =================
    for (int i = t; i < NHID*NHID; i += 256) sm[OFF_W + i] = Wad[i];
    __syncthreads();
    // q[n,k] = hd[n,:]·Wad[:,k] + bad[k]
    {
        const int k4 = (t & 31) * 4, g = t >> 5;       // n = g*4+i
        float4 acc[4];
        #pragma unroll
        for (int i = 0; i < 4; i++) acc[i] = make_float4(0.f, 0.f, 0.f, 0.f);
        for (int j = 0; j < NHID; j++) {
            float4 wv = *(const float4*)&sm[OFF_W + j*128 + k4];
            #pragma unroll
            for (int i = 0; i < 4; i++) {
                float hd = sm[OFF_HD + (g*4 + i)*NHID + j];
                acc[i].x += hd * wv.x; acc[i].y += hd * wv.y;
                acc[i].z += hd * wv.z; acc[i].w += hd * wv.w;
            }
        }
        float4 bb = *(const float4*)&bad[k4];
        #pragma unroll
        for (int i = 0; i < 4; i++) {
            int n = g*4 + i;
            float4 v = acc[i];
            v.x += bb.x; v.y += bb.y; v.z += bb.z; v.w += bb.w;
            *(float4*)&sm[OFF_Q + n*NHID + k4] = v;
        }
    }
    __syncthreads();
    for (int i = t; i < NHID*NHID; i += 256) sm[OFF_W + i] = Wak[i];
    __syncthreads();
    // k[m,k] = hk[m,:]·Wak[:,k] + bak[k]   (padded rows, KLD=132)
    {
        const int k4 = (t & 31) * 4, g = t >> 5;       // m = g*8+i
        float4 acc[8];
        #pragma unroll
        for (int i = 0; i < 8; i++) acc[i] = make_float4(0.f, 0.f, 0.f, 0.f);
        for (int j = 0; j < NHID; j++) {
            float4 wv = *(const float4*)&sm[OFF_W + j*128 + k4];
            #pragma unroll
            for (int i = 0; i < 8; i++) {
                float hk = sm[OFF_HK + (g*8 + i)*NHID + j];
                acc[i].x += hk * wv.x; acc[i].y += hk * wv.y;
                acc[i].z += hk * wv.z; acc[i].w += hk * wv.w;
            }
        }
        float4 bb = *(const float4*)&bak[k4];
        #pragma unroll
        for (int i = 0; i < 8; i++) {
            int m = g*8 + i;
            float4 v = acc[i];
            v.x += bb.x; v.y += bb.y; v.z += bb.z; v.w += bb.w;
            *(float4*)&sm[OFF_K + m*KLD + k4] = v;
        }
    }
    __syncthreads();
    // scores + mask -> logits
    for (int idx = t; idx < ND*NK; idx += 256) {
        int n = idx >> 6, m = idx & 63;
        const float* qp = &sm[OFF_Q + n*NHID];
        const float* kp = &sm[OFF_K + m*KLD];
        float a = 0.f;
        #pragma unroll
        for (int k = 0; k < NHID; k += 4) {
            float4 q4 = *(const float4*)&qp[k];
            float4 kv = *(const float4*)&kp[k];
            a += q4.x*kv.x + q4.y*kv.y + q4.z*kv.z + q4.w*kv.w;
        }
        out_logits[(size_t)b*2048 + idx] = (sm[OFF_ADJ + idx] > 0.f) ? a : NEGV;
    }
}

// ---- critic: values = relu(hd_flat @ Wc1 + bc1) @ Wc2 + bc2 ----
__global__ void __launch_bounds__(256, 1) critic_kernel(
    const float* __restrict__ Wc1, const float* __restrict__ bc1,
    const float* __restrict__ Wc2, const float* __restrict__ bc2,
    float* __restrict__ out_values)
{
    __shared__ float s_chunk[32 * 128];
    __shared__ float s_hidden[32 * 64];
    const int t = threadIdx.x;
    const int b0 = blockIdx.x * 32;
    const int j = t & 63, rg = t >> 6;   // rows rg*8 .. rg*8+7

    float acc[8];
    #pragma unroll
    for (int i = 0; i < 8; i++) acc[i] = 0.f;

    for (int i0 = 0; i0 < 4096; i0 += 128) {
        __syncthreads();
        for (int idx = t; idx < 32*128; idx += 256) {
            int r = idx >> 7, ii = idx & 127;
            s_chunk[idx] = g_hd[(size_t)(b0 + r) * 4096 + i0 + ii];
        }
        __syncthreads();
        for (int ii = 0; ii < 128; ii += 4) {
            float w0 = Wc1[(size_t)(i0 + ii    ) * 64 + j];
            float w1 = Wc1[(size_t)(i0 + ii + 1) * 64 + j];
            float w2 = Wc1[(size_t)(i0 + ii + 2) * 64 + j];
            float w3 = Wc1[(size_t)(i0 + ii + 3) * 64 + j];
            #pragma unroll
            for (int r = 0; r < 8; r++) {
                float4 h4 = *(const float4*)&s_chunk[(rg*8 + r)*128 + ii];
                acc[r] += h4.x*w0 + h4.y*w1 + h4.z*w2 + h4.w*w3;
            }
        }
    }
    float bj = bc1[j];
    #pragma unroll
    for (int r = 0; r < 8; r++) {
        float hdn = acc[r] + bj;
        s_hidden[(rg*8 + r)*64 + j] = hdn > 0.f ? hdn : 0.f;
    }
    __syncthreads();
    const int w = t >> 5, lane = t & 31;
    for (int r = w*4; r < w*4 + 4; r++) {
        float a = s_hidden[r*64 + lane] * Wc2[lane]
                + s_hidden[r*64 + lane + 32] * Wc2[lane + 32];
        #pragma unroll
        for (int o = 16; o > 0; o >>= 1) a += __shfl_xor_sync(0xffffffffu, a, o);
        if (lane == 0) out_values[b0 + r] = a + bc2[0];
    }
}

extern "C" void kernel_launch(void* const* d_in, const int* in_sizes, int n_in,
                              void* d_out, int out_size)
{
    const float* obs  = (const float*)d_in[0];
    const float* Wdr  = (const float*)d_in[1];
    const float* Wdk  = (const float*)d_in[2];
    const float* asrc = (const float*)d_in[3];
    const float* adst = (const float*)d_in[4];
    const float* Wc1  = (const float*)d_in[5];
    const float* bc1  = (const float*)d_in[6];
    const float* Wc2  = (const float*)d_in[7];
    const float* bc2  = (const float*)d_in[8];
    const float* Wad  = (const float*)d_in[9];
    const float* bad  = (const float*)d_in[10];
    const float* Wak  = (const float*)d_in[11];
    const float* bak  = (const float*)d_in[12];

    float* out        = (float*)d_out;
    float* out_values = out;            // [B]
    float* out_logits = out + NB;       // [B, 32, 64]

    cudaFuncSetAttribute(gat_main, cudaFuncAttributeMaxDynamicSharedMemorySize,
                         SMEM_FLOATS * (int)sizeof(float));

    gat_main<<<NB, 256, SMEM_FLOATS * sizeof(float)>>>(
        obs, Wdr, Wdk, asrc, adst, Wad, bad, Wak, bak, out_logits);
    critic_kernel<<<NB/32, 256>>>(Wc1, bc1, Wc2, bc2, out_values);
}

// round 2
// speedup vs baseline: 1.0055x; 1.0055x over previous
#include <cuda_runtime.h>

#define NB 4096
#define ND 32
#define NK 64
#define FD 16
#define FK 16
#define NHID 128
#define NH 4
#define ALPHA 0.2f
#define NEGV (-9e15f)

#define SD   (ND*FD)          // 512
#define SKK  (NK*FK)          // 1024
#define SADJ (ND*NK)          // 2048
#define OBSW (SD+SKK+SADJ)    // 3584

// ---- smem layout (float offsets) ----
#define OFF_ADJ   0                         // 2048
#define OFF_HD    2048                      // 32*128 = 4096
#define OFF_HK    (2048+4096)               // 64*128 = 8192
#define SBASE     (2048+4096+8192)          // 14336
// phase 1 (attention / projections)
#define OFF_DRONE (SBASE)                   // 512
#define OFF_DOCK  (SBASE+512)               // 1024
#define OFF_WDOCK (SBASE+1536)              // 8192
#define OFF_VSRC  (SBASE+9728)              // 64
#define OFF_VDST  (SBASE+9792)              // 64
#define OFF_SRC   (SBASE+9856)              // 128
#define OFF_DST   (SBASE+9984)              // 256
#define OFF_C     (SBASE+10240)             // 2048 (c, later wbar)
#define OFF_ATTN  (SBASE+12288)             // 512
// phase 2 (q/k/scores) -- aliases phase-1 scratch
#define OFF_W     (SBASE)                   // 16384
#define OFF_Q     (SBASE+16384)             // 4096
#define KLD       132
#define OFF_K     (SBASE+20480)             // 64*132 = 8448
#define SMEM_FLOATS (SBASE+20480+64*KLD)    // 43264 floats = 173056 B

__device__ float g_hd[(size_t)NB*ND*NHID];  // 64 MB scratch for h_drone

__device__ __forceinline__ float eluf(float x) { return x > 0.f ? x : expm1f(x); }

__global__ void __launch_bounds__(256, 1) gat_main(
    const float* __restrict__ obs,
    const float* __restrict__ Wdr, const float* __restrict__ Wdk,
    const float* __restrict__ asrc, const float* __restrict__ adst,
    const float* __restrict__ Wad, const float* __restrict__ bad,
    const float* __restrict__ Wak, const float* __restrict__ bak,
    float* __restrict__ out_logits)
{
    extern __shared__ float sm[];
    const int b = blockIdx.x;
    const int t = threadIdx.x;
    const float* row = obs + (size_t)b * OBSW;

    // ---- load obs row + W_dock ----
    for (int i = t; i < SD;   i += 256) sm[OFF_DRONE + i] = row[i];
    for (int i = t; i < SKK;  i += 256) sm[OFF_DOCK  + i] = row[SD + i];
    for (int i = t; i < SADJ; i += 256) sm[OFF_ADJ   + i] = row[SD + SKK + i];
    for (int i = t; i < NH*FK*NHID; i += 256) sm[OFF_WDOCK + i] = Wdk[i];
    __syncthreads();

    // ---- v_src[h,f] = W_drone[h,f,:]·a_src[h], v_dst similarly ----
    if (t < 64) {
        int h = t >> 4, f = t & 15;
        const float* wp = Wdr + (h*FD + f) * NHID;
        const float* ap = asrc + h * NHID;
        float a = 0.f;
        #pragma unroll 8
        for (int k = 0; k < NHID; k++) a += wp[k] * ap[k];
        sm[OFF_VSRC + t] = a;
    } else if (t < 128) {
        int u = t - 64, h = u >> 4, f = u & 15;
        const float* wp = &sm[OFF_WDOCK + (h*FK + f) * NHID];
        const float* ap = adst + h * NHID;
        float a = 0.f;
        #pragma unroll 8
        for (int k = 0; k < NHID; k++) a += wp[k] * ap[k];
        sm[OFF_VDST + u] = a;
    }
    __syncthreads();

    // ---- src[h,n], dst[h,m] ----
    if (t < 128) {
        int h = t >> 5, n = t & 31;
        float a = 0.f;
        #pragma unroll
        for (int f = 0; f < FD; f++) a += sm[OFF_DRONE + n*FD + f] * sm[OFF_VSRC + h*FD + f];
        sm[OFF_SRC + t] = a;
    }
    {
        int h = t >> 6, m = t & 63;
        float a = 0.f;
        #pragma unroll
        for (int f = 0; f < FK; f++) a += sm[OFF_DOCK + m*FK + f] * sm[OFF_VDST + h*FK + f];
        sm[OFF_DST + t] = a;
    }
    __syncthreads();

    // ---- attention rows: softmax over m, then c[h,n,:] = attn · dock ----
    {
        const int w = t >> 5, lane = t & 31;
        for (int r = w * 16; r < w * 16 + 16; r++) {
            int h = r >> 5, n = r & 31;
            float s0 = sm[OFF_SRC + h*32 + n];
            float e1, e2;
            {
                float e = s0 + sm[OFF_DST + h*64 + lane];
                e = e > 0.f ? e : ALPHA * e;
                if (!(sm[OFF_ADJ + n*64 + lane] > 0.f)) e = NEGV;
                e1 = e;
                e = s0 + sm[OFF_DST + h*64 + lane + 32];
                e = e > 0.f ? e : ALPHA * e;
                if (!(sm[OFF_ADJ + n*64 + lane + 32] > 0.f)) e = NEGV;
                e2 = e;
            }
            float mx = fmaxf(e1, e2);
            #pragma unroll
            for (int o = 16; o > 0; o >>= 1) mx = fmaxf(mx, __shfl_xor_sync(0xffffffffu, mx, o));
            float p1 = expf(e1 - mx), p2 = expf(e2 - mx);
            float s = p1 + p2;
            #pragma unroll
            for (int o = 16; o > 0; o >>= 1) s += __shfl_xor_sync(0xffffffffu, s, o);
            float inv = 1.0f / s;
            sm[OFF_ATTN + w*64 + lane]      = p1 * inv;
            sm[OFF_ATTN + w*64 + lane + 32] = p2 * inv;
            __syncwarp();
            if (lane < 16) {
                float a = 0.f;
                #pragma unroll 8
                for (int m = 0; m < 64; m++)
                    a += sm[OFF_ATTN + w*64 + m] * sm[OFF_DOCK + m*FK + lane];
                sm[OFF_C + r*16 + lane] = a;
            }
            __syncwarp();
        }
    }
    __syncthreads();

    // ---- h_drone[n,k] = elu( (1/4) * sum_{h,f} c[h,n,f] * Wdock[h,f,k] ) ----
    {
        const int k4 = (t & 31) * 4, g = t >> 5;       // g: 0..7, n = g*4+i
        float4 acc[4];
        #pragma unroll
        for (int i = 0; i < 4; i++) acc[i] = make_float4(0.f, 0.f, 0.f, 0.f);
        for (int h = 0; h < NH; h++)
            #pragma unroll
            for (int f = 0; f < FK; f++) {
                float4 wv = *(const float4*)&sm[OFF_WDOCK + (h*FK + f)*NHID + k4];
                #pragma unroll
                for (int i = 0; i < 4; i++) {
                    float c = sm[OFF_C + ((h*32) + g*4 + i)*16 + f];
                    acc[i].x += c * wv.x; acc[i].y += c * wv.y;
                    acc[i].z += c * wv.z; acc[i].w += c * wv.w;
                }
            }
        #pragma unroll
        for (int i = 0; i < 4; i++) {
            int n = g*4 + i;
            float4 v;
            v.x = eluf(acc[i].x * 0.25f); v.y = eluf(acc[i].y * 0.25f);
            v.z = eluf(acc[i].z * 0.25f); v.w = eluf(acc[i].w * 0.25f);
            *(float4*)&sm[OFF_HD + n*NHID + k4] = v;
            *(float4*)&g_hd[((size_t)b*ND + n)*NHID + k4] = v;
        }
    }
    __syncthreads();

    // ---- wbar[f,k] = mean_h Wdock[h,f,k]  (reuse c region) ----
    for (int i = t; i < FK*NHID; i += 256) {
        int f = i >> 7, k = i & 127;
        float a = sm[OFF_WDOCK + (f)*128 + k] + sm[OFF_WDOCK + (16+f)*128 + k]
                + sm[OFF_WDOCK + (32+f)*128 + k] + sm[OFF_WDOCK + (48+f)*128 + k];
        sm[OFF_C + i] = a * 0.25f;
    }
    __syncthreads();

    // ---- h_dock[m,k] = elu( dock[m,:] · wbar[:,k] ) ----
    {
        const int k4 = (t & 31) * 4, g = t >> 5;       // m = g*8+i
        float4 acc[8];
        #pragma unroll
        for (int i = 0; i < 8; i++) acc[i] = make_float4(0.f, 0.f, 0.f, 0.f);
        #pragma unroll
        for (int f = 0; f < FK; f++) {
            float4 wv = *(const float4*)&sm[OFF_C + f*128 + k4];
            #pragma unroll
            for (int i = 0; i < 8; i++) {
                float d = sm[OFF_DOCK + (g*8 + i)*FK + f];
                acc[i].x += d * wv.x; acc[i].y += d * wv.y;
                acc[i].z += d * wv.z; acc[i].w += d * wv.w;
            }
        }
        #pragma unroll
        for (int i = 0; i < 8; i++) {
            int m = g*8 + i;
            float4 v;
            v.x = eluf(acc[i].x); v.y = eluf(acc[i].y);
            v.z = eluf(acc[i].z); v.w = eluf(acc[i].w);
            *(float4*)&sm[OFF_HK + m*NHID + k4] = v;
        }
    }
    __syncthreads();

    // ================= phase 2: q, k, scores =================
    for (int i = t; i < NHID*NHID; i += 256) sm[OFF_W + i] = Wad[i];
    __syncthreads();
    // q[n,k] = hd[n,:]·Wad[:,k] + bad[k]
    {
        const int k4 = (t & 31) * 4, g = t >> 5;       // n = g*4+i
        float4 acc[4];
        #pragma unroll
        for (int i = 0; i < 4; i++) acc[i] = make_float4(0.f, 0.f, 0.f, 0.f);
        for (int j = 0; j < NHID; j++) {
            float4 wv = *(const float4*)&sm[OFF_W + j*128 + k4];
            #pragma unroll
            for (int i = 0; i < 4; i++) {
                float hd = sm[OFF_HD + (g*4 + i)*NHID + j];
                acc[i].x += hd * wv.x; acc[i].y += hd * wv.y;
                acc[i].z += hd * wv.z; acc[i].w += hd * wv.w;
            }
        }
        float4 bb = *(const float4*)&bad[k4];
        #pragma unroll
        for (int i = 0; i < 4; i++) {
            int n = g*4 + i;
            float4 v = acc[i];
            v.x += bb.x; v.y += bb.y; v.z += bb.z; v.w += bb.w;
            *(float4*)&sm[OFF_Q + n*NHID + k4] = v;
        }
    }
    __syncthreads();
    for (int i = t; i < NHID*NHID; i += 256) sm[OFF_W + i] = Wak[i];
    __syncthreads();
    // k[m,k] = hk[m,:]·Wak[:,k] + bak[k]   (padded rows, KLD=132)
    {
        const int k4 = (t & 31) * 4, g = t >> 5;       // m = g*8+i
        float4 acc[8];
        #pragma unroll
        for (int i = 0; i < 8; i++) acc[i] = make_float4(0.f, 0.f, 0.f, 0.f);
        for (int j = 0; j < NHID; j++) {
            float4 wv = *(const float4*)&sm[OFF_W + j*128 + k4];
            #pragma unroll
            for (int i = 0; i < 8; i++) {
                float hk = sm[OFF_HK + (g*8 + i)*NHID + j];
                acc[i].x += hk * wv.x; acc[i].y += hk * wv.y;
                acc[i].z += hk * wv.z; acc[i].w += hk * wv.w;
            }
        }
        float4 bb = *(const float4*)&bak[k4];
        #pragma unroll
        for (int i = 0; i < 8; i++) {
            int m = g*8 + i;
            float4 v = acc[i];
            v.x += bb.x; v.y += bb.y; v.z += bb.z; v.w += bb.w;
            *(float4*)&sm[OFF_K + m*KLD + k4] = v;
        }
    }
    __syncthreads();
    // scores + mask -> logits
    for (int idx = t; idx < ND*NK; idx += 256) {
        int n = idx >> 6, m = idx & 63;
        const float* qp = &sm[OFF_Q + n*NHID];
        const float* kp = &sm[OFF_K + m*KLD];
        float a = 0.f;
        #pragma unroll
        for (int k = 0; k < NHID; k += 4) {
            float4 q4 = *(const float4*)&qp[k];
            float4 kv = *(const float4*)&kp[k];
            a += q4.x*kv.x + q4.y*kv.y + q4.z*kv.z + q4.w*kv.w;
        }
        out_logits[(size_t)b*2048 + idx] = (sm[OFF_ADJ + idx] > 0.f) ? a : NEGV;
    }
}

// ---- critic: values = relu(hd_flat @ Wc1 + bc1) @ Wc2 + bc2 ----
__global__ void __launch_bounds__(256, 1) critic_kernel(
    const float* __restrict__ Wc1, const float* __restrict__ bc1,
    const float* __restrict__ Wc2, const float* __restrict__ bc2,
    float* __restrict__ out_values)
{
    __shared__ float s_chunk[32 * 128];
    __shared__ float s_hidden[32 * 64];
    const int t = threadIdx.x;
    const int b0 = blockIdx.x * 32;
    const int j = t & 63, rg = t >> 6;   // rows rg*8 .. rg*8+7

    float acc[8];
    #pragma unroll
    for (int i = 0; i < 8; i++) acc[i] = 0.f;

    for (int i0 = 0; i0 < 4096; i0 += 128) {
        __syncthreads();
        for (int idx = t; idx < 32*128; idx += 256) {
            int r = idx >> 7, ii = idx & 127;
            s_chunk[idx] = g_hd[(size_t)(b0 + r) * 4096 + i0 + ii];
        }
        __syncthreads();
        for (int ii = 0; ii < 128; ii += 4) {
            float w0 = Wc1[(size_t)(i0 + ii    ) * 64 + j];
            float w1 = Wc1[(size_t)(i0 + ii + 1) * 64 + j];
            float w2 = Wc1[(size_t)(i0 + ii + 2) * 64 + j];
            float w3 = Wc1[(size_t)(i0 + ii + 3) * 64 + j];
            #pragma unroll
            for (int r = 0; r < 8; r++) {
                float4 h4 = *(const float4*)&s_chunk[(rg*8 + r)*128 + ii];
                acc[r] += h4.x*w0 + h4.y*w1 + h4.z*w2 + h4.w*w3;
            }
        }
    }
    float bj = bc1[j];
    #pragma unroll
    for (int r = 0; r < 8; r++) {
        float hdn = acc[r] + bj;
        s_hidden[(rg*8 + r)*64 + j] = hdn > 0.f ? hdn : 0.f;
    }
    __syncthreads();
    const int w = t >> 5, lane = t & 31;
    for (int r = w*4; r < w*4 + 4; r++) {
        float a = s_hidden[r*64 + lane] * Wc2[lane]
                + s_hidden[r*64 + lane + 32] * Wc2[lane + 32];
        #pragma unroll
        for (int o = 16; o > 0; o >>= 1) a += __shfl_xor_sync(0xffffffffu, a, o);
        if (lane == 0) out_values[b0 + r] = a + bc2[0];
    }
}

extern "C" void kernel_launch(void* const* d_in, const int* in_sizes, int n_in,
                              void* d_out, int out_size)
{
    const float* obs  = (const float*)d_in[0];
    const float* Wdr  = (const float*)d_in[1];
    const float* Wdk  = (const float*)d_in[2];
    const float* asrc = (const float*)d_in[3];
    const float* adst = (const float*)d_in[4];
    const float* Wc1  = (const float*)d_in[5];
    const float* bc1  = (const float*)d_in[6];
    const float* Wc2  = (const float*)d_in[7];
    const float* bc2  = (const float*)d_in[8];
    const float* Wad  = (const float*)d_in[9];
    const float* bad  = (const float*)d_in[10];
    const float* Wak  = (const float*)d_in[11];
    const float* bak  = (const float*)d_in[12];

    float* out        = (float*)d_out;
    float* out_values = out;            // [B]
    float* out_logits = out + NB;       // [B, 32, 64]

    cudaFuncSetAttribute(gat_main, cudaFuncAttributeMaxDynamicSharedMemorySize,
                         SMEM_FLOATS * (int)sizeof(float));

    gat_main<<<NB, 256, SMEM_FLOATS * sizeof(float)>>>(
        obs, Wdr, Wdk, asrc, adst, Wad, bad, Wak, bak, out_logits);
    critic_kernel<<<NB/32, 256>>>(Wc1, bc1, Wc2, bc2, out_values);
}

// round 3
// speedup vs baseline: 2.0169x; 2.0060x over previous
#include <cuda_runtime.h>

#define NB 4096
#define ND 32
#define NK 64
#define NHID 128
#define ALPHA 0.2f
#define NEGV (-9e15f)
#define OBSW 3584
#define HKLD 132
#define RLD  132

// ---- gat_main smem layout (float offsets) ----
#define OFF_ADJ   0        // 2048
#define OFF_DOCK  2048     // 1024
#define OFF_DRONE 3072     // 512
#define OFF_HD    3584     // 4096
#define OFF_HK    7680     // 8448
#define OFF_R     16128    // 4224
#define OFF_SRC   20352    // 128
#define OFF_DST   20480    // 256
#define OFF_VS    20736    // 64
#define OFF_VD    20800    // 64
#define OFF_VB    20864    // 128
#define OFF_U     20992    // 128
#define OFF_T     21120    // 32
#define OFF_ATTN  21152    // 512 (64 per warp)
#define OFF_C     21664    // 2048
#define OFF_SCR   23712    // 4096 (Wdock pair / wbar / M quarter)
#define SMF       27808    // 111232 bytes

__device__ float g_hd[(size_t)NB * ND * NHID];   // 64 MB
__device__ float g_hpart[4ull * NB * 64];        // 4 MB critic partials
__device__ float g_M[NHID * NHID];
__device__ float g_vb[NHID];
__device__ float g_u[NHID];
__device__ float g_s0[1];
__device__ float g_vsrc[64];
__device__ float g_vdst[64];
__device__ float g_wbar[16 * NHID];

__device__ __forceinline__ float eluf(float x) { return x > 0.f ? x : expm1f(x); }

// ================= precompute (batch-independent), grid=17 =================
__global__ void precomp(const float* __restrict__ Wdr, const float* __restrict__ Wdk,
                        const float* __restrict__ asrc, const float* __restrict__ adst,
                        const float* __restrict__ Wad, const float* __restrict__ Wak,
                        const float* __restrict__ bad, const float* __restrict__ bak)
{
    const int t = threadIdx.x;
    if (blockIdx.x < 16) {
        __shared__ float swad[8 * 128];
        __shared__ float swak[32 * 128];
        const int a0 = blockIdx.x * 8;
        for (int i = t; i < 1024; i += 256) swad[i] = Wad[a0 * 128 + i];
        for (int jb = 0; jb < 4; jb++) {
            __syncthreads();
            for (int i = t; i < 4096; i += 256) swak[i] = Wak[jb * 4096 + i];
            __syncthreads();
            const int aa = t >> 5, jl = t & 31;
            float s = 0.f;
            for (int c = 0; c < 128; c++) {
                int cc = (c + jl) & 127;
                s += swad[aa * 128 + cc] * swak[jl * 128 + cc];
            }
            g_M[(a0 + aa) * 128 + jb * 32 + jl] = s;
        }
        if (t < 8) {
            float s = 0.f;
            for (int c = 0; c < 128; c++) s += swad[t * 128 + c] * bak[c];
            g_u[a0 + t] = s;
        }
    } else {
        __shared__ float sb[128];
        if (t < 128) sb[t] = bad[t];
        __syncthreads();
        if (t < 128) {
            float s = 0.f;
            for (int c = 0; c < 128; c++) s += sb[c] * Wak[t * 128 + c];
            g_vb[t] = s;
        }
        if (t == 0) {
            float s = 0.f;
            for (int c = 0; c < 128; c++) s += sb[c] * bak[c];
            g_s0[0] = s;
        }
        if (t < 64) {
            int h = t >> 4, f = t & 15;
            float s = 0.f;
            for (int c = 0; c < 128; c++) s += Wdr[(h * 16 + f) * 128 + c] * asrc[h * 128 + c];
            g_vsrc[t] = s;
        } else if (t < 128) {
            int u2 = t - 64, h = u2 >> 4, f = u2 & 15;
            float s = 0.f;
            for (int c = 0; c < 128; c++) s += Wdk[(h * 16 + f) * 128 + c] * adst[h * 128 + c];
            g_vdst[u2] = s;
        }
        for (int i = t; i < 2048; i += 256) {
            float s = Wdk[i] + Wdk[2048 + i] + Wdk[4096 + i] + Wdk[6144 + i];
            g_wbar[i] = s * 0.25f;
        }
    }
}

// ================= per-batch kernel =================
__global__ void __launch_bounds__(256, 2) gat_main(
    const float* __restrict__ obs, const float* __restrict__ Wdk,
    float* __restrict__ out_logits)
{
    extern __shared__ float sm[];
    const int b = blockIdx.x, t = threadIdx.x;
    const int w = t >> 5, lane = t & 31;
    const int k4 = lane * 4;
    const float* rowp = obs + (size_t)b * OBSW;

    for (int i = t; i < 512;  i += 256) sm[OFF_DRONE + i] = rowp[i];
    for (int i = t; i < 1024; i += 256) sm[OFF_DOCK  + i] = rowp[512 + i];
    for (int i = t; i < 2048; i += 256) sm[OFF_ADJ   + i] = rowp[1536 + i];
    if (t < 64)       sm[OFF_VS + t]       = g_vsrc[t];
    else if (t < 128) sm[OFF_VD + t - 64]  = g_vdst[t - 64];
    else              sm[OFF_VB + t - 128] = g_vb[t - 128];
    for (int i = t; i < 128; i += 256) sm[OFF_U + i] = g_u[i];
    __syncthreads();

    // src[h,n], dst[h,m]
    if (t < 128) {
        int h = t >> 5, n = t & 31;
        float s = 0.f;
        #pragma unroll
        for (int f = 0; f < 16; f++) s += sm[OFF_DRONE + n * 16 + f] * sm[OFF_VS + h * 16 + f];
        sm[OFF_SRC + t] = s;
    }
    {
        int h = t >> 6, m = t & 63;
        float s = 0.f;
        #pragma unroll
        for (int f = 0; f < 16; f++) s += sm[OFF_DOCK + m * 16 + f] * sm[OFF_VD + h * 16 + f];
        sm[OFF_DST + h * 64 + m] = s;
    }
    __syncthreads();

    // attention: softmax + c[r,f] = attn . dock   (warp w owns rows w*16..+15)
    {
        const int fl = lane & 15, mb = (lane >> 4) * 32;
        for (int r = w * 16; r < w * 16 + 16; r++) {
            int h = r >> 5, n = r & 31;
            float sc = sm[OFF_SRC + h * 32 + n];
            float e1 = sc + sm[OFF_DST + h * 64 + lane];
            e1 = e1 > 0.f ? e1 : ALPHA * e1;
            if (!(sm[OFF_ADJ + n * 64 + lane] > 0.f)) e1 = NEGV;
            float e2 = sc + sm[OFF_DST + h * 64 + 32 + lane];
            e2 = e2 > 0.f ? e2 : ALPHA * e2;
            if (!(sm[OFF_ADJ + n * 64 + 32 + lane] > 0.f)) e2 = NEGV;
            float mx = fmaxf(e1, e2);
            #pragma unroll
            for (int o = 16; o; o >>= 1) mx = fmaxf(mx, __shfl_xor_sync(~0u, mx, o));
            float p1 = __expf(e1 - mx), p2 = __expf(e2 - mx);
            float su = p1 + p2;
            #pragma unroll
            for (int o = 16; o; o >>= 1) su += __shfl_xor_sync(~0u, su, o);
            float inv = 1.0f / su;
            sm[OFF_ATTN + w * 64 + lane]      = p1 * inv;
            sm[OFF_ATTN + w * 64 + 32 + lane] = p2 * inv;
            __syncwarp();
            float cc = 0.f;
            #pragma unroll 8
            for (int mm = 0; mm < 32; mm++)
                cc += sm[OFF_ATTN + w * 64 + mb + mm] * sm[OFF_DOCK + (mb + mm) * 16 + fl];
            cc += __shfl_xor_sync(~0u, cc, 16);
            if (lane < 16) sm[OFF_C + r * 16 + fl] = cc;
            __syncwarp();
        }
    }
    __syncthreads();

    // h_drone: accumulate over 2 head-pair passes (stage Wdock pair in SCR)
    float4 hacc[4] = {};
    for (int hp = 0; hp < 2; hp++) {
        for (int i = t; i < 1024; i += 256)
            *(float4*)&sm[OFF_SCR + i * 4] = *(const float4*)&Wdk[hp * 4096 + i * 4];
        __syncthreads();
        #pragma unroll
        for (int hf = 0; hf < 32; hf++) {
            float4 wv = *(float4*)&sm[OFF_SCR + hf * 128 + k4];
            int crow = (hp * 2 + (hf >> 4)) * 32 + w * 4;
            #pragma unroll
            for (int i = 0; i < 4; i++) {
                float cv = sm[OFF_C + (crow + i) * 16 + (hf & 15)];
                hacc[i].x += cv * wv.x; hacc[i].y += cv * wv.y;
                hacc[i].z += cv * wv.z; hacc[i].w += cv * wv.w;
            }
        }
        __syncthreads();
    }
    #pragma unroll
    for (int i = 0; i < 4; i++) {
        int n = w * 4 + i;
        float4 v;
        v.x = eluf(hacc[i].x * 0.25f); v.y = eluf(hacc[i].y * 0.25f);
        v.z = eluf(hacc[i].z * 0.25f); v.w = eluf(hacc[i].w * 0.25f);
        *(float4*)&sm[OFF_HD + n * 128 + k4] = v;
        *(float4*)&g_hd[((size_t)b * ND + n) * 128 + k4] = v;
    }

    // h_dock: stage wbar, warp w owns m = w*8..+7
    for (int i = t; i < 512; i += 256)
        *(float4*)&sm[OFF_SCR + i * 4] = *(const float4*)&g_wbar[i * 4];
    __syncthreads();
    {
        float4 acc[8] = {};
        #pragma unroll
        for (int f = 0; f < 16; f++) {
            float4 wv = *(float4*)&sm[OFF_SCR + f * 128 + k4];
            #pragma unroll
            for (int i = 0; i < 8; i++) {
                float d = sm[OFF_DOCK + (w * 8 + i) * 16 + f];
                acc[i].x += d * wv.x; acc[i].y += d * wv.y;
                acc[i].z += d * wv.z; acc[i].w += d * wv.w;
            }
        }
        #pragma unroll
        for (int i = 0; i < 8; i++) {
            float4 v;
            v.x = eluf(acc[i].x); v.y = eluf(acc[i].y);
            v.z = eluf(acc[i].z); v.w = eluf(acc[i].w);
            *(float4*)&sm[OFF_HK + (w * 8 + i) * HKLD + k4] = v;
        }
    }
    __syncthreads();

    // r = hd @ M + vb  (M staged in 4 quarters; warp w owns n = w*4..+3)
    {
        float4 acc[4] = {};
        for (int q = 0; q < 4; q++) {
            for (int i = t; i < 1024; i += 256)
                *(float4*)&sm[OFF_SCR + i * 4] = *(const float4*)&g_M[q * 4096 + i * 4];
            __syncthreads();
            #pragma unroll 8
            for (int a = 0; a < 32; a++) {
                float4 wv = *(float4*)&sm[OFF_SCR + a * 128 + k4];
                #pragma unroll
                for (int i = 0; i < 4; i++) {
                    float hv = sm[OFF_HD + (w * 4 + i) * 128 + q * 32 + a];
                    acc[i].x += hv * wv.x; acc[i].y += hv * wv.y;
                    acc[i].z += hv * wv.z; acc[i].w += hv * wv.w;
                }
            }
            __syncthreads();
        }
        float4 bb = *(float4*)&sm[OFF_VB + k4];
        #pragma unroll
        for (int i = 0; i < 4; i++) {
            float4 v = acc[i];
            v.x += bb.x; v.y += bb.y; v.z += bb.z; v.w += bb.w;
            *(float4*)&sm[OFF_R + (w * 4 + i) * RLD + k4] = v;
        }
    }
    // t[n] = hd[n,:].u + s0
    if (t < 32) {
        float s = g_s0[0];
        for (int aa = 0; aa < 128; aa++) {
            int a = (aa + t) & 127;
            s += sm[OFF_HD + t * 128 + a] * sm[OFF_U + a];
        }
        sm[OFF_T + t] = s;
    }
    __syncthreads();

    // logits[n,m] = mask ? r[n].hk[m] + t[n] : NEG
    {
        const int n = t >> 3, m0 = t & 7;
        float acc[8] = {};
        #pragma unroll 4
        for (int j = 0; j < 128; j++) {
            float rv = sm[OFF_R + n * RLD + j];
            #pragma unroll
            for (int i = 0; i < 8; i++)
                acc[i] += rv * sm[OFF_HK + (m0 + 8 * i) * HKLD + j];
        }
        float tn = sm[OFF_T + n];
        float* outp = out_logits + (size_t)b * 2048 + n * 64;
        #pragma unroll
        for (int i = 0; i < 8; i++) {
            int m = m0 + 8 * i;
            outp[m] = (sm[OFF_ADJ + n * 64 + m] > 0.f) ? (acc[i] + tn) : NEGV;
        }
    }
}

// ================= critic: split-K GEMM then combine =================
__global__ void __launch_bounds__(256) critic_gemm(const float* __restrict__ Wc1)
{
    __shared__ float s_chunk[32 * 128];
    const int t = threadIdx.x;
    const int b0 = blockIdx.x * 32;
    const int kb = blockIdx.y * 1024;
    const int j = t & 63, rg = t >> 6;
    float acc[8] = {};

    for (int c = 0; c < 8; c++) {
        const int kbase = kb + c * 128;
        __syncthreads();
        for (int idx = t; idx < 1024; idx += 256) {
            int r = idx >> 5, c4 = (idx & 31) * 4;
            *(float4*)&s_chunk[r * 128 + c4] =
                *(const float4*)&g_hd[(size_t)(b0 + r) * 4096 + kbase + c4];
        }
        __syncthreads();
        for (int ii = 0; ii < 128; ii += 4) {
            float w0 = Wc1[(size_t)(kbase + ii    ) * 64 + j];
            float w1 = Wc1[(size_t)(kbase + ii + 1) * 64 + j];
            float w2 = Wc1[(size_t)(kbase + ii + 2) * 64 + j];
            float w3 = Wc1[(size_t)(kbase + ii + 3) * 64 + j];
            #pragma unroll
            for (int r = 0; r < 8; r++) {
                float4 h4 = *(const float4*)&s_chunk[(rg * 8 + r) * 128 + ii];
                acc[r] += h4.x * w0 + h4.y * w1 + h4.z * w2 + h4.w * w3;
            }
        }
    }
    #pragma unroll
    for (int r = 0; r < 8; r++)
        g_hpart[((size_t)blockIdx.y * NB + b0 + rg * 8 + r) * 64 + j] = acc[r];
}

__global__ void __launch_bounds__(256) critic_final(
    const float* __restrict__ bc1, const float* __restrict__ Wc2,
    const float* __restrict__ bc2, float* __restrict__ out_values)
{
    const int w = threadIdx.x >> 5, lane = threadIdx.x & 31;
    const int b = blockIdx.x * 8 + w;
    float a = 0.f;
    #pragma unroll
    for (int half = 0; half < 2; half++) {
        int jj = lane + 32 * half;
        size_t o = (size_t)b * 64 + jj;
        float h = g_hpart[o] + g_hpart[(size_t)NB * 64 + o]
                + g_hpart[2ull * NB * 64 + o] + g_hpart[3ull * NB * 64 + o] + bc1[jj];
        a += (h > 0.f ? h : 0.f) * Wc2[jj];
    }
    #pragma unroll
    for (int o = 16; o; o >>= 1) a += __shfl_xor_sync(~0u, a, o);
    if (lane == 0) out_values[b] = a + bc2[0];
}

extern "C" void kernel_launch(void* const* d_in, const int* in_sizes, int n_in,
                              void* d_out, int out_size)
{
    const float* obs  = (const float*)d_in[0];
    const float* Wdr  = (const float*)d_in[1];
    const float* Wdk  = (const float*)d_in[2];
    const float* asrc = (const float*)d_in[3];
    const float* adst = (const float*)d_in[4];
    const float* Wc1  = (const float*)d_in[5];
    const float* bc1  = (const float*)d_in[6];
    const float* Wc2  = (const float*)d_in[7];
    const float* bc2  = (const float*)d_in[8];
    const float* Wad  = (const float*)d_in[9];
    const float* bad  = (const float*)d_in[10];
    const float* Wak  = (const float*)d_in[11];
    const float* bak  = (const float*)d_in[12];

    float* out        = (float*)d_out;
    float* out_values = out;
    float* out_logits = out + NB;

    cudaFuncSetAttribute(gat_main, cudaFuncAttributeMaxDynamicSharedMemorySize,
                         SMF * (int)sizeof(float));

    precomp<<<17, 256>>>(Wdr, Wdk, asrc, adst, Wad, Wak, bad, bak);
    gat_main<<<NB, 256, SMF * sizeof(float)>>>(obs, Wdk, out_logits);
    critic_gemm<<<dim3(NB / 32, 4), 256>>>(Wc1);
    critic_final<<<NB / 8, 256>>>(bc1, Wc2, bc2, out_values);
}

// round 4
// speedup vs baseline: 2.2891x; 1.1350x over previous
#include <cuda_runtime.h>

#define NB 4096
#define ND 32
#define NK 64
#define NHID 128
#define ALPHA 0.2f
#define NEGV (-9e15f)
#define OBSW 3584

// ---- gat_main smem layout (float offsets) ----
#define OFF_ADJ   0        // 2048
#define OFF_DOCKT 2048     // 16*68 = 1088   dockT[f][m]
#define DKTLD 68
#define OFF_DRONE 3136     // 512
#define OFF_HDT   3648     // 128*36 = 4608  hdT[a][n]
#define HDTLD 36
#define OFF_HKT   8256     // 128*68 = 8704  hkT[k][m]
#define HKTLD 68
#define OFF_RT    16960    // 128*36 = 4608  rT[j][n]  (aliases cT)
#define RTLD 36
#define OFF_CT    16960    // 16*132 = 2112  cT[f][r]
#define CTLD 132
#define OFF_SCR   21568    // 4096 staging (Wdock pair / wbar / M quarter)
#define OFF_ATTN  25664    // 512 (64 per warp)
#define OFF_SRC   26176    // 128
#define OFF_DST   26304    // 256
#define OFF_VS    26560    // 64
#define OFF_VD    26624    // 64
#define OFF_VB    26688    // 128
#define OFF_U     26816    // 128
#define OFF_T     26944    // 32
#define SMF       26976    // 107904 bytes

__device__ float g_hd[(size_t)NB * ND * NHID];   // 64 MB
__device__ float g_hpart[8ull * NB * 64];        // 8 MB critic partials
__device__ float g_M[NHID * NHID];
__device__ float g_vb[NHID];
__device__ float g_u[NHID];
__device__ float g_s0[1];
__device__ float g_vsrc[64];
__device__ float g_vdst[64];
__device__ float g_wbar[16 * NHID];

__device__ __forceinline__ float eluf(float x) { return x > 0.f ? x : expm1f(x); }

// ================= precompute (batch-independent), grid=17 =================
__global__ void precomp(const float* __restrict__ Wdr, const float* __restrict__ Wdk,
                        const float* __restrict__ asrc, const float* __restrict__ adst,
                        const float* __restrict__ Wad, const float* __restrict__ Wak,
                        const float* __restrict__ bad, const float* __restrict__ bak)
{
    const int t = threadIdx.x;
    if (blockIdx.x < 16) {
        __shared__ float swad[8 * 128];
        __shared__ float swak[32 * 128];
        const int a0 = blockIdx.x * 8;
        for (int i = t; i < 1024; i += 256) swad[i] = Wad[a0 * 128 + i];
        for (int jb = 0; jb < 4; jb++) {
            __syncthreads();
            for (int i = t; i < 4096; i += 256) swak[i] = Wak[jb * 4096 + i];
            __syncthreads();
            const int aa = t >> 5, jl = t & 31;
            float s = 0.f;
            for (int c = 0; c < 128; c++) {
                int cc = (c + jl) & 127;
                s += swad[aa * 128 + cc] * swak[jl * 128 + cc];
            }
            g_M[(a0 + aa) * 128 + jb * 32 + jl] = s;
        }
        if (t < 8) {
            float s = 0.f;
            for (int c = 0; c < 128; c++) s += swad[t * 128 + c] * bak[c];
            g_u[a0 + t] = s;
        }
    } else {
        __shared__ float sb[128];
        if (t < 128) sb[t] = bad[t];
        __syncthreads();
        if (t < 128) {
            float s = 0.f;
            for (int c = 0; c < 128; c++) s += sb[c] * Wak[t * 128 + c];
            g_vb[t] = s;
        }
        if (t == 0) {
            float s = 0.f;
            for (int c = 0; c < 128; c++) s += sb[c] * bak[c];
            g_s0[0] = s;
        }
        if (t < 64) {
            int h = t >> 4, f = t & 15;
            float s = 0.f;
            for (int c = 0; c < 128; c++) s += Wdr[(h * 16 + f) * 128 + c] * asrc[h * 128 + c];
            g_vsrc[t] = s;
        } else if (t < 128) {
            int u2 = t - 64, h = u2 >> 4, f = u2 & 15;
            float s = 0.f;
            for (int c = 0; c < 128; c++) s += Wdk[(h * 16 + f) * 128 + c] * adst[h * 128 + c];
            g_vdst[u2] = s;
        }
        for (int i = t; i < 2048; i += 256) {
            float s = Wdk[i] + Wdk[2048 + i] + Wdk[4096 + i] + Wdk[6144 + i];
            g_wbar[i] = s * 0.25f;
        }
    }
}

// ================= per-batch kernel =================
__global__ void __launch_bounds__(256, 2) gat_main(
    const float* __restrict__ obs, const float* __restrict__ Wdk,
    float* __restrict__ out_logits)
{
    extern __shared__ float sm[];
    const int b = blockIdx.x, t = threadIdx.x;
    const int w = t >> 5, lane = t & 31;
    const int k4 = lane * 4;
    const float* rowp = obs + (size_t)b * OBSW;

    for (int i = t; i < 512;  i += 256) sm[OFF_DRONE + i] = rowp[i];
    for (int i = t; i < 1024; i += 256) {
        int m = i >> 4, f = i & 15;
        sm[OFF_DOCKT + f * DKTLD + m] = rowp[512 + i];
    }
    for (int i = t; i < 2048; i += 256) sm[OFF_ADJ + i] = rowp[1536 + i];
    if (t < 64)       sm[OFF_VS + t]       = g_vsrc[t];
    else if (t < 128) sm[OFF_VD + t - 64]  = g_vdst[t - 64];
    else              sm[OFF_VB + t - 128] = g_vb[t - 128];
    for (int i = t; i < 128; i += 256) sm[OFF_U + i] = g_u[i];
    __syncthreads();

    // src[h,n], dst[h,m]
    if (t < 128) {
        int h = t >> 5, n = t & 31;
        float s = 0.f;
        #pragma unroll
        for (int f = 0; f < 16; f++) s += sm[OFF_DRONE + n * 16 + f] * sm[OFF_VS + h * 16 + f];
        sm[OFF_SRC + t] = s;
    }
    {
        int h = t >> 6, m = t & 63;
        float s = 0.f;
        #pragma unroll
        for (int f = 0; f < 16; f++) s += sm[OFF_DOCKT + f * DKTLD + m] * sm[OFF_VD + h * 16 + f];
        sm[OFF_DST + h * 64 + m] = s;
    }
    __syncthreads();

    // attention: softmax + cT[f][r] = attn . dock   (warp w owns rows w*16..+15)
    {
        const int fl = lane & 15, mb = (lane >> 4) * 32;
        for (int r = w * 16; r < w * 16 + 16; r++) {
            int h = r >> 5, n = r & 31;
            float sc = sm[OFF_SRC + h * 32 + n];
            float e1 = sc + sm[OFF_DST + h * 64 + lane];
            e1 = e1 > 0.f ? e1 : ALPHA * e1;
            if (!(sm[OFF_ADJ + n * 64 + lane] > 0.f)) e1 = NEGV;
            float e2 = sc + sm[OFF_DST + h * 64 + 32 + lane];
            e2 = e2 > 0.f ? e2 : ALPHA * e2;
            if (!(sm[OFF_ADJ + n * 64 + 32 + lane] > 0.f)) e2 = NEGV;
            float mx = fmaxf(e1, e2);
            #pragma unroll
            for (int o = 16; o; o >>= 1) mx = fmaxf(mx, __shfl_xor_sync(~0u, mx, o));
            float p1 = __expf(e1 - mx), p2 = __expf(e2 - mx);
            float su = p1 + p2;
            #pragma unroll
            for (int o = 16; o; o >>= 1) su += __shfl_xor_sync(~0u, su, o);
            float inv = 1.0f / su;
            sm[OFF_ATTN + w * 64 + lane]      = p1 * inv;
            sm[OFF_ATTN + w * 64 + 32 + lane] = p2 * inv;
            __syncwarp();
            float cc = 0.f;
            #pragma unroll
            for (int mm = 0; mm < 32; mm += 4) {
                float4 av = *(float4*)&sm[OFF_ATTN + w * 64 + mb + mm];
                float4 dv = *(float4*)&sm[OFF_DOCKT + fl * DKTLD + mb + mm];
                cc += av.x * dv.x + av.y * dv.y + av.z * dv.z + av.w * dv.w;
            }
            cc += __shfl_xor_sync(~0u, cc, 16);
            if (lane < 16) sm[OFF_CT + fl * CTLD + r] = cc;
            __syncwarp();
        }
    }
    __syncthreads();

    // h_drone: 2 head-pair passes, Wdock pair staged in SCR
    float4 hacc[4] = {};
    for (int hp = 0; hp < 2; hp++) {
        for (int i = t; i < 1024; i += 256)
            *(float4*)&sm[OFF_SCR + i * 4] = *(const float4*)&Wdk[hp * 4096 + i * 4];
        __syncthreads();
        #pragma unroll
        for (int hf = 0; hf < 32; hf++) {
            float4 wv = *(float4*)&sm[OFF_SCR + hf * 128 + k4];
            float4 cv = *(float4*)&sm[OFF_CT + (hf & 15) * CTLD + (hp * 2 + (hf >> 4)) * 32 + w * 4];
            hacc[0].x += cv.x * wv.x; hacc[0].y += cv.x * wv.y; hacc[0].z += cv.x * wv.z; hacc[0].w += cv.x * wv.w;
            hacc[1].x += cv.y * wv.x; hacc[1].y += cv.y * wv.y; hacc[1].z += cv.y * wv.z; hacc[1].w += cv.y * wv.w;
            hacc[2].x += cv.z * wv.x; hacc[2].y += cv.z * wv.y; hacc[2].z += cv.z * wv.z; hacc[2].w += cv.z * wv.w;
            hacc[3].x += cv.w * wv.x; hacc[3].y += cv.w * wv.y; hacc[3].z += cv.w * wv.z; hacc[3].w += cv.w * wv.w;
        }
        __syncthreads();
    }
    // finalize h_drone -> g_hd (n-major) + hdT (smem)
    {
        float4 ho[4];
        #pragma unroll
        for (int i = 0; i < 4; i++) {
            ho[i].x = eluf(hacc[i].x * 0.25f); ho[i].y = eluf(hacc[i].y * 0.25f);
            ho[i].z = eluf(hacc[i].z * 0.25f); ho[i].w = eluf(hacc[i].w * 0.25f);
            *(float4*)&g_hd[((size_t)b * ND + w * 4 + i) * 128 + k4] = ho[i];
        }
        float4 c0 = make_float4(ho[0].x, ho[1].x, ho[2].x, ho[3].x);
        float4 c1 = make_float4(ho[0].y, ho[1].y, ho[2].y, ho[3].y);
        float4 c2 = make_float4(ho[0].z, ho[1].z, ho[2].z, ho[3].z);
        float4 c3 = make_float4(ho[0].w, ho[1].w, ho[2].w, ho[3].w);
        *(float4*)&sm[OFF_HDT + (k4 + 0) * HDTLD + w * 4] = c0;
        *(float4*)&sm[OFF_HDT + (k4 + 1) * HDTLD + w * 4] = c1;
        *(float4*)&sm[OFF_HDT + (k4 + 2) * HDTLD + w * 4] = c2;
        *(float4*)&sm[OFF_HDT + (k4 + 3) * HDTLD + w * 4] = c3;
    }

    // h_dock: stage wbar, tile 8m x 4k per thread -> hkT[k][m]
    for (int i = t; i < 512; i += 256)
        *(float4*)&sm[OFF_SCR + i * 4] = *(const float4*)&g_wbar[i * 4];
    __syncthreads();
    {
        const int m0 = (t & 7) * 8, k0 = (t >> 3) * 4;
        float4 acc[8] = {};
        #pragma unroll
        for (int f = 0; f < 16; f++) {
            float4 wv = *(float4*)&sm[OFF_SCR + f * 128 + k0];
            float4 da = *(float4*)&sm[OFF_DOCKT + f * DKTLD + m0];
            float4 db = *(float4*)&sm[OFF_DOCKT + f * DKTLD + m0 + 4];
            acc[0].x += da.x * wv.x; acc[0].y += da.x * wv.y; acc[0].z += da.x * wv.z; acc[0].w += da.x * wv.w;
            acc[1].x += da.y * wv.x; acc[1].y += da.y * wv.y; acc[1].z += da.y * wv.z; acc[1].w += da.y * wv.w;
            acc[2].x += da.z * wv.x; acc[2].y += da.z * wv.y; acc[2].z += da.z * wv.z; acc[2].w += da.z * wv.w;
            acc[3].x += da.w * wv.x; acc[3].y += da.w * wv.y; acc[3].z += da.w * wv.z; acc[3].w += da.w * wv.w;
            acc[4].x += db.x * wv.x; acc[4].y += db.x * wv.y; acc[4].z += db.x * wv.z; acc[4].w += db.x * wv.w;
            acc[5].x += db.y * wv.x; acc[5].y += db.y * wv.y; acc[5].z += db.y * wv.z; acc[5].w += db.y * wv.w;
            acc[6].x += db.z * wv.x; acc[6].y += db.z * wv.y; acc[6].z += db.z * wv.z; acc[6].w += db.z * wv.w;
            acc[7].x += db.w * wv.x; acc[7].y += db.w * wv.y; acc[7].z += db.w * wv.z; acc[7].w += db.w * wv.w;
        }
        float4 va, vb4;
        va = make_float4(eluf(acc[0].x), eluf(acc[1].x), eluf(acc[2].x), eluf(acc[3].x));
        vb4 = make_float4(eluf(acc[4].x), eluf(acc[5].x), eluf(acc[6].x), eluf(acc[7].x));
        *(float4*)&sm[OFF_HKT + (k0 + 0) * HKTLD + m0] = va;
        *(float4*)&sm[OFF_HKT + (k0 + 0) * HKTLD + m0 + 4] = vb4;
        va = make_float4(eluf(acc[0].y), eluf(acc[1].y), eluf(acc[2].y), eluf(acc[3].y));
        vb4 = make_float4(eluf(acc[4].y), eluf(acc[5].y), eluf(acc[6].y), eluf(acc[7].y));
        *(float4*)&sm[OFF_HKT + (k0 + 1) * HKTLD + m0] = va;
        *(float4*)&sm[OFF_HKT + (k0 + 1) * HKTLD + m0 + 4] = vb4;
        va = make_float4(eluf(acc[0].z), eluf(acc[1].z), eluf(acc[2].z), eluf(acc[3].z));
        vb4 = make_float4(eluf(acc[4].z), eluf(acc[5].z), eluf(acc[6].z), eluf(acc[7].z));
        *(float4*)&sm[OFF_HKT + (k0 + 2) * HKTLD + m0] = va;
        *(float4*)&sm[OFF_HKT + (k0 + 2) * HKTLD + m0 + 4] = vb4;
        va = make_float4(eluf(acc[0].w), eluf(acc[1].w), eluf(acc[2].w), eluf(acc[3].w));
        vb4 = make_float4(eluf(acc[4].w), eluf(acc[5].w), eluf(acc[6].w), eluf(acc[7].w));
        *(float4*)&sm[OFF_HKT + (k0 + 3) * HKTLD + m0] = va;
        *(float4*)&sm[OFF_HKT + (k0 + 3) * HKTLD + m0 + 4] = vb4;
    }
    __syncthreads();

    // r = hd @ M + vb, stored transposed rT[j][n]; M staged in 4 quarters
    {
        const int n0 = (t & 7) * 4, j0 = (t >> 3) * 4;
        float4 acc[4] = {};   // acc[i] = r[n0+i][j0..j0+3]
        for (int q = 0; q < 4; q++) {
            for (int i = t; i < 1024; i += 256)
                *(float4*)&sm[OFF_SCR + i * 4] = *(const float4*)&g_M[q * 4096 + i * 4];
            __syncthreads();
            #pragma unroll 8
            for (int al = 0; al < 32; al++) {
                float4 mv = *(float4*)&sm[OFF_SCR + al * 128 + j0];
                float4 hv = *(float4*)&sm[OFF_HDT + (q * 32 + al) * HDTLD + n0];
                acc[0].x += hv.x * mv.x; acc[0].y += hv.x * mv.y; acc[0].z += hv.x * mv.z; acc[0].w += hv.x * mv.w;
                acc[1].x += hv.y * mv.x; acc[1].y += hv.y * mv.y; acc[1].z += hv.y * mv.z; acc[1].w += hv.y * mv.w;
                acc[2].x += hv.z * mv.x; acc[2].y += hv.z * mv.y; acc[2].z += hv.z * mv.z; acc[2].w += hv.z * mv.w;
                acc[3].x += hv.w * mv.x; acc[3].y += hv.w * mv.y; acc[3].z += hv.w * mv.z; acc[3].w += hv.w * mv.w;
            }
            __syncthreads();
        }
        float4 bb = *(float4*)&sm[OFF_VB + j0];
        #pragma unroll
        for (int i = 0; i < 4; i++) {
            acc[i].x += bb.x; acc[i].y += bb.y; acc[i].z += bb.z; acc[i].w += bb.w;
        }
        float4 c0 = make_float4(acc[0].x, acc[1].x, acc[2].x, acc[3].x);
        float4 c1 = make_float4(acc[0].y, acc[1].y, acc[2].y, acc[3].y);
        float4 c2 = make_float4(acc[0].z, acc[1].z, acc[2].z, acc[3].z);
        float4 c3 = make_float4(acc[0].w, acc[1].w, acc[2].w, acc[3].w);
        *(float4*)&sm[OFF_RT + (j0 + 0) * RTLD + n0] = c0;
        *(float4*)&sm[OFF_RT + (j0 + 1) * RTLD + n0] = c1;
        *(float4*)&sm[OFF_RT + (j0 + 2) * RTLD + n0] = c2;
        *(float4*)&sm[OFF_RT + (j0 + 3) * RTLD + n0] = c3;
    }
    // t[n] = hd[n,:].u + s0
    if (t < 32) {
        float s = g_s0[0];
        #pragma unroll 8
        for (int a = 0; a < 128; a++) s += sm[OFF_HDT + a * HDTLD + t] * sm[OFF_U + a];
        sm[OFF_T + t] = s;
    }
    __syncthreads();

    // logits[n,m] = mask ? rT.hkT + t[n] : NEG    (tile 2n x 4m per thread)
    {
        const int n0 = (t >> 4) * 2, m0 = (t & 15) * 4;
        float4 a0 = make_float4(0.f, 0.f, 0.f, 0.f);
        float4 a1 = make_float4(0.f, 0.f, 0.f, 0.f);
        #pragma unroll 4
        for (int j = 0; j < 128; j++) {
            float2 rv = *(float2*)&sm[OFF_RT + j * RTLD + n0];
            float4 hv = *(float4*)&sm[OFF_HKT + j * HKTLD + m0];
            a0.x += rv.x * hv.x; a0.y += rv.x * hv.y; a0.z += rv.x * hv.z; a0.w += rv.x * hv.w;
            a1.x += rv.y * hv.x; a1.y += rv.y * hv.y; a1.z += rv.y * hv.z; a1.w += rv.y * hv.w;
        }
        float t0 = sm[OFF_T + n0], t1 = sm[OFF_T + n0 + 1];
        float4 j0v = *(float4*)&sm[OFF_ADJ + n0 * 64 + m0];
        float4 j1v = *(float4*)&sm[OFF_ADJ + (n0 + 1) * 64 + m0];
        float4 o0, o1;
        o0.x = j0v.x > 0.f ? a0.x + t0 : NEGV; o0.y = j0v.y > 0.f ? a0.y + t0 : NEGV;
        o0.z = j0v.z > 0.f ? a0.z + t0 : NEGV; o0.w = j0v.w > 0.f ? a0.w + t0 : NEGV;
        o1.x = j1v.x > 0.f ? a1.x + t1 : NEGV; o1.y = j1v.y > 0.f ? a1.y + t1 : NEGV;
        o1.z = j1v.z > 0.f ? a1.z + t1 : NEGV; o1.w = j1v.w > 0.f ? a1.w + t1 : NEGV;
        float* op = out_logits + (size_t)b * 2048;
        *(float4*)&op[n0 * 64 + m0] = o0;
        *(float4*)&op[(n0 + 1) * 64 + m0] = o1;
    }
}

// ================= critic: split-K(8) GEMM then combine =================
__global__ void __launch_bounds__(256) critic_gemm(const float* __restrict__ Wc1)
{
    __shared__ float s_chunk[32 * 128];
    const int t = threadIdx.x;
    const int b0 = blockIdx.x * 32;
    const int kb = blockIdx.y * 512;
    const int j = t & 63, rg = t >> 6;
    float acc[8] = {};

    for (int c = 0; c < 4; c++) {
        const int kbase = kb + c * 128;
        __syncthreads();
        for (int idx = t; idx < 1024; idx += 256) {
            int r = idx >> 5, c4 = (idx & 31) * 4;
            *(float4*)&s_chunk[r * 128 + c4] =
                *(const float4*)&g_hd[(size_t)(b0 + r) * 4096 + kbase + c4];
        }
        __syncthreads();
        for (int ii = 0; ii < 128; ii += 4) {
            float w0 = Wc1[(size_t)(kbase + ii    ) * 64 + j];
            float w1 = Wc1[(size_t)(kbase + ii + 1) * 64 + j];
            float w2 = Wc1[(size_t)(kbase + ii + 2) * 64 + j];
            float w3 = Wc1[(size_t)(kbase + ii + 3) * 64 + j];
            #pragma unroll
            for (int r = 0; r < 8; r++) {
                float4 h4 = *(const float4*)&s_chunk[(rg * 8 + r) * 128 + ii];
                acc[r] += h4.x * w0 + h4.y * w1 + h4.z * w2 + h4.w * w3;
            }
        }
    }
    #pragma unroll
    for (int r = 0; r < 8; r++)
        g_hpart[((size_t)blockIdx.y * NB + b0 + rg * 8 + r) * 64 + j] = acc[r];
}

__global__ void __launch_bounds__(256) critic_final(
    const float* __restrict__ bc1, const float* __restrict__ Wc2,
    const float* __restrict__ bc2, float* __restrict__ out_values)
{
    const int w = threadIdx.x >> 5, lane = threadIdx.x & 31;
    const int b = blockIdx.x * 8 + w;
    float a = 0.f;
    #pragma unroll
    for (int half = 0; half < 2; half++) {
        int jj = lane + 32 * half;
        size_t o = (size_t)b * 64 + jj;
        float h = bc1[jj];
        #pragma unroll
        for (int p = 0; p < 8; p++) h += g_hpart[(size_t)p * NB * 64 + o];
        a += (h > 0.f ? h : 0.f) * Wc2[jj];
    }
    #pragma unroll
    for (int o = 16; o; o >>= 1) a += __shfl_xor_sync(~0u, a, o);
    if (lane == 0) out_values[b] = a + bc2[0];
}

extern "C" void kernel_launch(void* const* d_in, const int* in_sizes, int n_in,
                              void* d_out, int out_size)
{
    const float* obs  = (const float*)d_in[0];
    const float* Wdr  = (const float*)d_in[1];
    const float* Wdk  = (const float*)d_in[2];
    const float* asrc = (const float*)d_in[3];
    const float* adst = (const float*)d_in[4];
    const float* Wc1  = (const float*)d_in[5];
    const float* bc1  = (const float*)d_in[6];
    const float* Wc2  = (const float*)d_in[7];
    const float* bc2  = (const float*)d_in[8];
    const float* Wad  = (const float*)d_in[9];
    const float* bad  = (const float*)d_in[10];
    const float* Wak  = (const float*)d_in[11];
    const float* bak  = (const float*)d_in[12];

    float* out        = (float*)d_out;
    float* out_values = out;
    float* out_logits = out + NB;

    cudaFuncSetAttribute(gat_main, cudaFuncAttributeMaxDynamicSharedMemorySize,
                         SMF * (int)sizeof(float));

    precomp<<<17, 256>>>(Wdr, Wdk, asrc, adst, Wad, Wak, bad, bak);
    gat_main<<<NB, 256, SMF * sizeof(float)>>>(obs, Wdk, out_logits);
    critic_gemm<<<dim3(NB / 32, 8), 256>>>(Wc1);
    critic_final<<<NB / 8, 256>>>(bc1, Wc2, bc2, out_values);
}